// round 6
// baseline (speedup 1.0000x reference)
#include <cuda_runtime.h>
#include <cuda_bf16.h>
#include <cstdint>
#include <cstddef>

#define BATCH 8192

// ----------------------------- static scratch ------------------------------
__device__ __align__(16) signed char    g_y1[(size_t)BATCH * 400 * 32]; // 104.9 MB
__device__ __align__(16) unsigned       g_a1[BATCH * 400];              // packed L1 acts (bit=ch)
__device__ __align__(16) short          g_y2[(size_t)BATCH * 144 * 16]; // 37.7 MB
__device__ __align__(16) unsigned short g_a2[BATCH * 144];              // packed L2 acts (16 ch bits)
__device__ __align__(16) short          g_y3[BATCH * 128];              // [n][pos(16)][c(8)]
__device__ __align__(16) unsigned       g_a3[BATCH * 4];                // 128 bits / image

__device__ unsigned       g_w1p[32 * 9];     // [f][u], bits v=0..8
__device__ unsigned       g_w2p[16 * 81];    // [f][tap], bits c=0..31
__device__ unsigned short g_w3p[8 * 81];     // [f][tap], bits c=0..15
__device__ unsigned       g_wlp[10 * 4];     // [f][p], bit (c + 8q), pos=4p+q
__device__ float          g_sbl[10];

__device__ unsigned long long g_s1[32], g_s2[16], g_s3[8];
__device__ int                g_t1[32], g_t2[16], g_t3[8]; // integer thresholds ceil(mean)

// ------------------------------ prep (weights pack + zero sums) ------------
__global__ void prepk(const float* __restrict__ w1, const float* __restrict__ w2,
                      const float* __restrict__ w3, const float* __restrict__ wl,
                      const float* __restrict__ bl) {
    int idx = blockIdx.x * blockDim.x + threadIdx.x;
    if (idx < 288) {                       // w1: (32,1,9,9)
        int f = idx / 9, u = idx % 9;
        unsigned m = 0;
        for (int v = 0; v < 9; v++)
            if (w1[f * 81 + u * 9 + v] >= 0.f) m |= 1u << v;
        g_w1p[idx] = m;
    } else if (idx < 288 + 1296) {         // w2: (16,32,9,9)
        int e = idx - 288, f = e / 81, t = e % 81;
        unsigned m = 0;
        for (int c = 0; c < 32; c++)
            if (w2[f * 2592 + c * 81 + t] >= 0.f) m |= 1u << c;
        g_w2p[e] = m;
    } else if (idx < 1584 + 648) {         // w3: (8,16,9,9)
        int e = idx - 1584, f = e / 81, t = e % 81;
        unsigned m = 0;
        for (int c = 0; c < 16; c++)
            if (w3[f * 1296 + c * 81 + t] >= 0.f) m |= 1u << c;
        g_w3p[e] = (unsigned short)m;
    } else if (idx < 2232 + 40) {          // wl: (10,8,4,4)
        int e = idx - 2232, f = e / 4, p = e % 4;
        unsigned m = 0;
        for (int q = 0; q < 4; q++)
            for (int c = 0; c < 8; c++)
                if (wl[f * 128 + c * 16 + (4 * p + q)] >= 0.f) m |= 1u << (c + 8 * q);
        g_wlp[e] = m;
    } else if (idx < 2272 + 10) {
        int f = idx - 2272;
        g_sbl[f] = (bl[f] >= 0.f) ? 1.f : -1.f;
    } else if (idx < 2282 + 32) { g_s1[idx - 2282] = 0ull; }
    else if (idx < 2314 + 16)   { g_s2[idx - 2314] = 0ull; }
    else if (idx < 2330 + 8)    { g_s3[idx - 2330] = 0ull; }
}

// ------------------------------ conv1 --------------------------------------
// x (1,28,28) fp32 -> binarize -> 9x9 conv, 32 filters -> y1 int8 (20,20,32)
__global__ __launch_bounds__(256) void conv1k(const float* __restrict__ x) {
    __shared__ unsigned xr[28];     // packed rows, bit j = (x[i][j] >= 0)
    __shared__ unsigned ws[288];
    __shared__ int bsum[32];
    int tid = threadIdx.x, n = blockIdx.x;
    int lane = tid & 31, warp = tid >> 5;
    if (tid < 32) bsum[tid] = 0;
    for (int t = tid; t < 288; t += 256) ws[t] = g_w1p[t];   // FIXED: strided
    const float* xi = x + (size_t)n * 784;
    for (int row = warp; row < 28; row += 8) {
        float v = (lane < 28) ? xi[row * 28 + lane] : -1.f;
        unsigned m = __ballot_sync(0xFFFFFFFFu, v >= 0.f);
        if (lane == 0) xr[row] = m;
    }
    __syncthreads();

    int fsum = 0;
    int myf = tid & 31;
    for (int t = tid; t < 640; t += 256) {      // task = (row i, filter f)
        int f = t & 31, i = t >> 5;
        unsigned w[9], r[9];
#pragma unroll
        for (int u = 0; u < 9; u++) { w[u] = ws[f * 9 + u]; r[u] = xr[i + u]; }
        signed char* yp = g_y1 + ((size_t)n * 400 + (size_t)i * 20) * 32 + f;
#pragma unroll 4
        for (int j = 0; j < 20; j++) {
            int acc = 0;
#pragma unroll
            for (int u = 0; u < 9; u++)
                acc += __popc(((r[u] >> j) & 0x1FFu) ^ w[u]);
            int y = 81 - 2 * acc;
            yp[j * 32] = (signed char)y;
            fsum += y;
        }
    }
    atomicAdd(&bsum[myf], fsum);
    __syncthreads();
    if (tid < 32) atomicAdd(&g_s1[tid], (unsigned long long)(long long)bsum[tid]);
}

// ------------------------------ means -> integer thresholds ----------------
__global__ void meank(int stage) {
    int t = threadIdx.x;
    if (stage == 0 && t < 32) g_t1[t] = (int)ceil((double)(long long)g_s1[t] / 3276800.0);
    if (stage == 1 && t < 16) g_t2[t] = (int)ceil((double)(long long)g_s2[t] / 1179648.0);
    if (stage == 2 && t < 8)  g_t3[t] = (int)ceil((double)(long long)g_s3[t] / 131072.0);
}

// ------------------------------ pack1 (binarize y1 -> a1) ------------------
__global__ __launch_bounds__(256) void pack1k() {
    __shared__ int ts[32];
    if (threadIdx.x < 32) ts[threadIdx.x] = g_t1[threadIdx.x];
    __syncthreads();
    int p = blockIdx.x * 256 + threadIdx.x;    // pixel index < 3,276,800
    const uint4* yp = (const uint4*)(g_y1 + (size_t)p * 32);
    uint4 A = yp[0], B = yp[1];
    unsigned q[8] = {A.x, A.y, A.z, A.w, B.x, B.y, B.z, B.w};
    unsigned word = 0;
#pragma unroll
    for (int wi = 0; wi < 8; wi++) {
#pragma unroll
        for (int k = 0; k < 4; k++) {
            int sb = (int)(q[wi] << (24 - 8 * k)) >> 24;
            if (sb >= ts[wi * 4 + k]) word |= 1u << (wi * 4 + k);
        }
    }
    g_a1[p] = word;
}

// ------------------------------ conv2 --------------------------------------
// a1 (32ch packed, 20x20) -> 9x9 conv, 16 filters -> y2 int16 (12,12,16)
__global__ __launch_bounds__(256) void conv2k() {
    __shared__ unsigned xs[400];
    __shared__ unsigned ws[1296];
    __shared__ int bsum[16];
    int tid = threadIdx.x, n = blockIdx.x;
    if (tid < 16) bsum[tid] = 0;
    for (int t = tid; t < 400; t += 256) xs[t] = g_a1[n * 400 + t];
    for (int t = tid; t < 1296; t += 256) ws[t] = g_w2p[t];
    __syncthreads();

    int fsum = 0;
    int myf = tid & 15;
    for (int t = tid; t < 576; t += 256) {      // task = (f, row i, j-quad)
        int f = t & 15, r = t >> 4;             // r in 0..35
        int i = r / 3, j4 = (r % 3) * 4;
        const unsigned* wp = &ws[f * 81];
        int a0 = 0, a1 = 0, a2 = 0, a3 = 0;
#pragma unroll
        for (int u = 0; u < 9; u++) {
            unsigned xw[12];
#pragma unroll
            for (int v = 0; v < 12; v++) xw[v] = xs[(i + u) * 20 + j4 + v];
#pragma unroll
            for (int v = 0; v < 9; v++) {
                unsigned w = wp[u * 9 + v];
                a0 += __popc(xw[v + 0] ^ w);
                a1 += __popc(xw[v + 1] ^ w);
                a2 += __popc(xw[v + 2] ^ w);
                a3 += __popc(xw[v + 3] ^ w);
            }
        }
        int pix = i * 12 + j4;
        short* yp = g_y2 + ((size_t)n * 144 + pix) * 16 + f;
        int y0 = 2592 - 2 * a0, y1 = 2592 - 2 * a1;
        int y2 = 2592 - 2 * a2, y3 = 2592 - 2 * a3;
        yp[0] = (short)y0; yp[16] = (short)y1; yp[32] = (short)y2; yp[48] = (short)y3;
        fsum += y0 + y1 + y2 + y3;
    }
    atomicAdd(&bsum[myf], fsum);
    __syncthreads();
    if (tid < 16) atomicAdd(&g_s2[tid], (unsigned long long)(long long)bsum[tid]);
}

// ------------------------------ pack2 --------------------------------------
__global__ __launch_bounds__(256) void pack2k() {
    __shared__ int ts[16];
    if (threadIdx.x < 16) ts[threadIdx.x] = g_t2[threadIdx.x];
    __syncthreads();
    int p = blockIdx.x * 256 + threadIdx.x;    // pixel < 1,179,648
    const uint4* yp = (const uint4*)(g_y2 + (size_t)p * 16);
    uint4 A = yp[0], B = yp[1];
    unsigned q[8] = {A.x, A.y, A.z, A.w, B.x, B.y, B.z, B.w};
    unsigned word = 0;
#pragma unroll
    for (int wi = 0; wi < 8; wi++) {
        int lo = (int)(q[wi] << 16) >> 16;
        int hi = (int)q[wi] >> 16;
        if (lo >= ts[2 * wi + 0]) word |= 1u << (2 * wi + 0);
        if (hi >= ts[2 * wi + 1]) word |= 1u << (2 * wi + 1);
    }
    g_a2[p] = (unsigned short)word;
}

// ------------------------------ conv3 --------------------------------------
// a2 (16ch packed, 12x12) -> 9x9 conv, 8 filters -> y3 int16 (4,4,8)
__global__ __launch_bounds__(128) void conv3k() {
    __shared__ unsigned short xs[144];
    __shared__ unsigned short ws[648];
    __shared__ int bsum[8];
    int tid = threadIdx.x, n = blockIdx.x;
    if (tid < 8) bsum[tid] = 0;
    for (int t = tid; t < 144; t += 128) xs[t] = g_a2[n * 144 + t];   // FIXED: strided
    for (int t = tid; t < 648; t += 128) ws[t] = g_w3p[t];
    __syncthreads();

    int f = tid & 7, pix = tid >> 3, i = pix >> 2, j = pix & 3;
    int acc = 0;
#pragma unroll
    for (int u = 0; u < 9; u++)
#pragma unroll
        for (int v = 0; v < 9; v++)
            acc += __popc((unsigned)(xs[(i + u) * 12 + j + v] ^ ws[f * 81 + u * 9 + v]));
    int y = 1296 - 2 * acc;
    g_y3[n * 128 + pix * 8 + f] = (short)y;
    atomicAdd(&bsum[f], y);
    __syncthreads();
    if (tid < 8) atomicAdd(&g_s3[tid], (unsigned long long)(long long)bsum[tid]);
}

// ------------------------------ pack3 --------------------------------------
__global__ __launch_bounds__(256) void pack3k() {
    int n = blockIdx.x * 256 + threadIdx.x;    // image < 8192
    int ts[8];
#pragma unroll
    for (int c = 0; c < 8; c++) ts[c] = g_t3[c];
    const short* y = g_y3 + (size_t)n * 128;
    unsigned wd[4] = {0, 0, 0, 0};
#pragma unroll
    for (int pos = 0; pos < 16; pos++)
#pragma unroll
        for (int c = 0; c < 8; c++)
            if ((int)y[pos * 8 + c] >= ts[c]) wd[pos >> 2] |= 1u << (c + 8 * (pos & 3));
#pragma unroll
    for (int p = 0; p < 4; p++) g_a3[n * 4 + p] = wd[p];
}

// ------------------------------ layer 4 (linear conv, +sign(bl)) -----------
__global__ __launch_bounds__(256) void out4k(float* __restrict__ out) {
    int idx = blockIdx.x * 256 + threadIdx.x;  // < 81920
    int n = idx / 10, f = idx - 10 * n;
    const unsigned* a = g_a3 + n * 4;
    const unsigned* wp = g_wlp + f * 4;
    int pop = 0;
#pragma unroll
    for (int p = 0; p < 4; p++) pop += __popc(a[p] ^ wp[p]);
    out[idx] = (float)(128 - 2 * pop) + g_sbl[f];
}

// ------------------------------ launch -------------------------------------
// Inputs identified BY ELEMENT COUNT (all 9 distinct): robust to any order.
//   x  : 6422528   w1 : 2592   w2 : 41472   w3 : 10368   wl : 1280
//   b1 : 32        b2 : 16     b3 : 8       bl : 10   (b1/b2/b3 cancel)
extern "C" void kernel_launch(void* const* d_in, const int* in_sizes, int n_in,
                              void* d_out, int out_size) {
    (void)out_size;
    const float *x = 0, *w1 = 0, *w2 = 0, *w3 = 0, *wl = 0, *bl = 0;
    for (int i = 0; i < n_in; i++) {
        const float* p = (const float*)d_in[i];
        switch (in_sizes[i]) {
            case 6422528: x  = p; break;
            case 2592:    w1 = p; break;
            case 41472:   w2 = p; break;
            case 10368:   w3 = p; break;
            case 1280:    wl = p; break;
            case 10:      bl = p; break;
            default: break;
        }
    }

    prepk<<<10, 256>>>(w1, w2, w3, wl, bl);
    conv1k<<<BATCH, 256>>>(x);
    meank<<<1, 32>>>(0);
    pack1k<<<12800, 256>>>();
    conv2k<<<BATCH, 256>>>();
    meank<<<1, 32>>>(1);
    pack2k<<<4608, 256>>>();
    conv3k<<<BATCH, 128>>>();
    meank<<<1, 32>>>(2);
    pack3k<<<32, 256>>>();
    out4k<<<320, 256>>>((float*)d_out);
}